// round 7
// baseline (speedup 1.0000x reference)
#include <cuda_runtime.h>
#include <cuda_bf16.h>

// Problem constants
#define B_SZ   512
#define T_SZ   256
#define C_SZ   384
#define H_SZ   64
#define SCALE  0.125f   // 64^-0.5

// Scratch for Q, K, V projections (no cudaMalloc allowed -> __device__ globals)
__device__ float g_Q[B_SZ * T_SZ * H_SZ];
__device__ float g_K[B_SZ * T_SZ * H_SZ];
__device__ float g_V[B_SZ * T_SZ * H_SZ];

typedef unsigned long long ull_t;

// ---------- packed f32x2 helpers (sm_100+ only; ptxas never auto-emits these) ----------
__device__ __forceinline__ void ffma2(ull_t& d, ull_t a, ull_t b) {
    asm("fma.rn.f32x2 %0, %1, %2, %0;" : "+l"(d) : "l"(a), "l"(b));
}
__device__ __forceinline__ ull_t add2(ull_t a, ull_t b) {
    ull_t r; asm("add.rn.f32x2 %0, %1, %2;" : "=l"(r) : "l"(a), "l"(b)); return r;
}
__device__ __forceinline__ ull_t mul2(ull_t a, ull_t b) {
    ull_t r; asm("mul.rn.f32x2 %0, %1, %2;" : "=l"(r) : "l"(a), "l"(b)); return r;
}
__device__ __forceinline__ ull_t pack2(float lo, float hi) {
    ull_t r; asm("mov.b64 %0, {%1, %2};" : "=l"(r) : "f"(lo), "f"(hi)); return r;
}
__device__ __forceinline__ void unpack2(ull_t v, float& lo, float& hi) {
    asm("mov.b64 {%0, %1}, %2;" : "=f"(lo), "=f"(hi) : "l"(v));
}

// ============================================================================
// Kernel 1: fused QKV projection.
// GEMM: [131072 x 384] @ [384 x 64] for each of Wq/Wk/Wv, + bias.
// Tile: BM=64 rows, N=64 (full), Ktile=32. 256 threads (16x16), each thread
// computes a 4x4 output micro-tile per matrix (as 4x2 f32x2 pairs).
// ============================================================================
__global__ __launch_bounds__(256) void qkv_kernel(
    const float* __restrict__ x,
    const float* __restrict__ Wq, const float* __restrict__ bq,
    const float* __restrict__ Wk, const float* __restrict__ bk,
    const float* __restrict__ Wv, const float* __restrict__ bv)
{
    __shared__ __align__(16) float As[64 * 32];
    __shared__ __align__(16) float Bs[3][32 * 64];

    const int tid  = threadIdx.x;
    const int tx   = tid & 15;        // output col group: cols tx*4 .. tx*4+3
    const int ty   = tid >> 4;        // output row group: rows ty*4 .. ty*4+3
    const int row0 = blockIdx.x << 6; // 64 rows per block

    ull_t acc[3][4][2];
    #pragma unroll
    for (int m = 0; m < 3; m++)
        #pragma unroll
        for (int i = 0; i < 4; i++) { acc[m][i][0] = 0ULL; acc[m][i][1] = 0ULL; }

    for (int kt = 0; kt < C_SZ; kt += 32) {
        // --- stage A tile: 64x32 floats = 512 float4, 2 per thread ---
        #pragma unroll
        for (int it = 0; it < 2; it++) {
            int u = tid + it * 256;
            int r = u >> 3, c = (u & 7) << 2;
            *(float4*)&As[r * 32 + c] =
                *(const float4*)&x[(size_t)(row0 + r) * C_SZ + kt + c];
        }
        // --- stage B tiles: 32x64 floats each = 512 float4, 2 per thread per matrix ---
        #pragma unroll
        for (int it = 0; it < 2; it++) {
            int u = tid + it * 256;
            int r = u >> 4, c = (u & 15) << 2;
            *(float4*)&Bs[0][r * 64 + c] = *(const float4*)&Wq[(kt + r) * H_SZ + c];
            *(float4*)&Bs[1][r * 64 + c] = *(const float4*)&Wk[(kt + r) * H_SZ + c];
            *(float4*)&Bs[2][r * 64 + c] = *(const float4*)&Wv[(kt + r) * H_SZ + c];
        }
        __syncthreads();

        #pragma unroll 8
        for (int kk = 0; kk < 32; kk++) {
            ull_t a2[4];
            #pragma unroll
            for (int i = 0; i < 4; i++) {
                float a = As[(ty * 4 + i) * 32 + kk];
                a2[i] = pack2(a, a);
            }
            #pragma unroll
            for (int m = 0; m < 3; m++) {
                ulonglong2 b2 = *(const ulonglong2*)&Bs[m][kk * 64 + tx * 4];
                #pragma unroll
                for (int i = 0; i < 4; i++) {
                    ffma2(acc[m][i][0], a2[i], b2.x);
                    ffma2(acc[m][i][1], a2[i], b2.y);
                }
            }
        }
        __syncthreads();
    }

    // --- bias + store ---
    const float* biases[3] = { bq, bk, bv };
    float* outs[3] = { g_Q, g_K, g_V };
    #pragma unroll
    for (int m = 0; m < 3; m++) {
        ull_t blo = *(const ull_t*)&biases[m][tx * 4];
        ull_t bhi = *(const ull_t*)&biases[m][tx * 4 + 2];
        #pragma unroll
        for (int i = 0; i < 4; i++) {
            ulonglong2 st;
            st.x = add2(acc[m][i][0], blo);
            st.y = add2(acc[m][i][1], bhi);
            *(ulonglong2*)&outs[m][(size_t)(row0 + ty * 4 + i) * H_SZ + tx * 4] = st;
        }
    }
}

// ============================================================================
// Kernel 2: causal attention, one block per batch, one query row per thread.
// K and V staged in 128 KB dynamic smem (broadcast reads: all lanes read the
// same k/v row at each step -> conflict-free). Online (flash) softmax with
// branch-gated rescale; accumulator and q held in registers as f32x2 pairs.
// ============================================================================
__global__ __launch_bounds__(256) void attn_kernel(float* __restrict__ out)
{
    extern __shared__ __align__(16) float sm[];
    float* Ks = sm;                    // 256*64 floats
    float* Vs = sm + T_SZ * H_SZ;      // 256*64 floats

    const int b   = blockIdx.x;
    const int t   = threadIdx.x;       // query row (0..255)
    const size_t base = (size_t)b * T_SZ * H_SZ;

    // stage K, V (16384 floats each = 4096 float4 each)
    {
        const float4* gk = (const float4*)(g_K + base);
        const float4* gv = (const float4*)(g_V + base);
        for (int u = t; u < 4096; u += 256) {
            ((float4*)Ks)[u] = gk[u];
            ((float4*)Vs)[u] = gv[u];
        }
    }
    __syncthreads();

    // load this thread's q row into registers (32 packed pairs)
    ull_t q2[32];
    {
        const ulonglong2* qg = (const ulonglong2*)(g_Q + base + (size_t)t * H_SZ);
        #pragma unroll
        for (int h = 0; h < 16; h++) {
            ulonglong2 v = qg[h];
            q2[2 * h]     = v.x;
            q2[2 * h + 1] = v.y;
        }
    }

    ull_t acc2[32];
    #pragma unroll
    for (int h = 0; h < 32; h++) acc2[h] = 0ULL;

    float m = -1e30f;
    float l = 0.0f;

    for (int s = 0; s <= t; s++) {
        // --- score = scale * dot(q, k[s]) ---
        ull_t d0 = 0ULL, d1 = 0ULL, d2p = 0ULL, d3 = 0ULL;
        const ulonglong2* kr = (const ulonglong2*)(Ks + (s << 6));
        #pragma unroll
        for (int h = 0; h < 16; h += 2) {
            ulonglong2 ka = kr[h];
            ulonglong2 kb = kr[h + 1];
            ffma2(d0, q2[2 * h],     ka.x);
            ffma2(d1, q2[2 * h + 1], ka.y);
            ffma2(d2p, q2[2 * h + 2], kb.x);
            ffma2(d3, q2[2 * h + 3], kb.y);
        }
        float lo, hi;
        unpack2(add2(add2(d0, d1), add2(d2p, d3)), lo, hi);
        float score = (lo + hi) * SCALE;

        // --- online softmax update ---
        if (score > m) {
            float c = __expf(m - score);   // 0 on first iteration (m = -1e30)
            m = score;
            l *= c;
            ull_t c2 = pack2(c, c);
            #pragma unroll
            for (int h = 0; h < 32; h++) acc2[h] = mul2(acc2[h], c2);
        }
        float p = __expf(score - m);
        l += p;

        // --- acc += p * v[s] ---
        ull_t p2 = pack2(p, p);
        const ulonglong2* vr = (const ulonglong2*)(Vs + (s << 6));
        #pragma unroll
        for (int h = 0; h < 16; h++) {
            ulonglong2 vv = vr[h];
            ffma2(acc2[2 * h],     p2, vv.x);
            ffma2(acc2[2 * h + 1], p2, vv.y);
        }
    }

    // --- normalize and store ---
    float inv = 1.0f / l;
    ull_t inv2 = pack2(inv, inv);
    float* op = out + base + (size_t)t * H_SZ;
    #pragma unroll
    for (int h = 0; h < 16; h++) {
        ulonglong2 st;
        st.x = mul2(acc2[2 * h],     inv2);
        st.y = mul2(acc2[2 * h + 1], inv2);
        *(ulonglong2*)&op[h * 4] = st;
    }
}

// ============================================================================
extern "C" void kernel_launch(void* const* d_in, const int* in_sizes, int n_in,
                              void* d_out, int out_size)
{
    const float* x  = (const float*)d_in[0];
    const float* Wq = (const float*)d_in[1];
    const float* bq = (const float*)d_in[2];
    const float* Wk = (const float*)d_in[3];
    const float* bk = (const float*)d_in[4];
    const float* Wv = (const float*)d_in[5];
    const float* bv = (const float*)d_in[6];
    float* out = (float*)d_out;

    // 128 KB dynamic smem for attn kernel (opt-in; idempotent, capture-safe)
    static int smem_set = 0;
    if (!smem_set) {
        cudaFuncSetAttribute(attn_kernel,
                             cudaFuncAttributeMaxDynamicSharedMemorySize,
                             2 * T_SZ * H_SZ * (int)sizeof(float));
        smem_set = 1;
    }

    // QKV projection: 131072 rows / 64 rows per block
    qkv_kernel<<<(B_SZ * T_SZ) / 64, 256>>>(x, Wq, bq, Wk, bk, Wv, bv);

    // Attention: one block per batch
    attn_kernel<<<B_SZ, 256, 2 * T_SZ * H_SZ * (int)sizeof(float)>>>(out);
}

// round 8
// speedup vs baseline: 2.0862x; 2.0862x over previous
#include <cuda_runtime.h>
#include <cuda_bf16.h>

// Problem constants
#define B_SZ   512
#define T_SZ   256
#define C_SZ   384
#define H_SZ   64
#define SCALE  0.125f   // 64^-0.5

// Scratch for Q, K, V projections (no cudaMalloc allowed -> __device__ globals)
__device__ float g_Q[B_SZ * T_SZ * H_SZ];
__device__ float g_K[B_SZ * T_SZ * H_SZ];
__device__ float g_V[B_SZ * T_SZ * H_SZ];

typedef unsigned long long ull_t;

// ---------- packed f32x2 helpers (sm_100+ only; ptxas never auto-emits these) ----------
__device__ __forceinline__ void ffma2(ull_t& d, ull_t a, ull_t b) {
    asm("fma.rn.f32x2 %0, %1, %2, %0;" : "+l"(d) : "l"(a), "l"(b));
}
__device__ __forceinline__ ull_t add2(ull_t a, ull_t b) {
    ull_t r; asm("add.rn.f32x2 %0, %1, %2;" : "=l"(r) : "l"(a), "l"(b)); return r;
}
__device__ __forceinline__ ull_t mul2(ull_t a, ull_t b) {
    ull_t r; asm("mul.rn.f32x2 %0, %1, %2;" : "=l"(r) : "l"(a), "l"(b)); return r;
}
__device__ __forceinline__ ull_t pack2(float lo, float hi) {
    ull_t r; asm("mov.b64 %0, {%1, %2};" : "=l"(r) : "f"(lo), "f"(hi)); return r;
}
__device__ __forceinline__ void unpack2(ull_t v, float& lo, float& hi) {
    asm("mov.b64 {%0, %1}, %2;" : "=f"(lo), "=f"(hi) : "l"(v));
}

// ============================================================================
// Kernel 1: fused QKV projection (BM=128, Ktile=32, 512 threads).
// GEMM: [131072 x 384] @ [384 x 64] x3 (+bias). Each thread: 4x4 micro-tile
// per matrix as f32x2 pairs. gmem->reg prefetch overlaps LDG with compute.
// ============================================================================
#define APAD 36   // As row stride (128 rows x 36): breaks 4-row bank aliasing, 16B-aligned

__global__ __launch_bounds__(512) void qkv_kernel(
    const float* __restrict__ x,
    const float* __restrict__ Wq, const float* __restrict__ bq,
    const float* __restrict__ Wk, const float* __restrict__ bk,
    const float* __restrict__ Wv, const float* __restrict__ bv)
{
    __shared__ __align__(16) float As[128 * APAD];
    __shared__ __align__(16) float Bs[3][32 * 64];

    const int tid  = threadIdx.x;
    const int tx   = tid & 15;        // output col group: cols tx*4 .. tx*4+3
    const int ty   = tid >> 4;        // output row group (0..31): rows ty*4 .. ty*4+3
    const int row0 = blockIdx.x << 7; // 128 rows per block

    // staging index precompute
    const int ar0 = tid >> 3,        ac0 = (tid & 7) << 2;   // A part 0 (u = tid)
    const int ar1 = (tid + 512) >> 3, ac1 = ac0;             // A part 1 (u = tid+512)
    const int br  = tid >> 4,        bc  = (tid & 15) << 2;  // B (u = tid)

    ull_t acc[3][4][2];
    #pragma unroll
    for (int m = 0; m < 3; m++)
        #pragma unroll
        for (int i = 0; i < 4; i++) { acc[m][i][0] = 0ULL; acc[m][i][1] = 0ULL; }

    // prefetch tile 0 into registers
    float4 a_pf0 = *(const float4*)&x[(size_t)(row0 + ar0) * C_SZ + ac0];
    float4 a_pf1 = *(const float4*)&x[(size_t)(row0 + ar1) * C_SZ + ac1];
    float4 b_pf0 = *(const float4*)&Wq[br * H_SZ + bc];
    float4 b_pf1 = *(const float4*)&Wk[br * H_SZ + bc];
    float4 b_pf2 = *(const float4*)&Wv[br * H_SZ + bc];

    for (int kt = 0; kt < C_SZ; kt += 32) {
        // store prefetched tile to smem (prev compute drained by trailing sync)
        *(float4*)&As[ar0 * APAD + ac0] = a_pf0;
        *(float4*)&As[ar1 * APAD + ac1] = a_pf1;
        *(float4*)&Bs[0][br * 64 + bc] = b_pf0;
        *(float4*)&Bs[1][br * 64 + bc] = b_pf1;
        *(float4*)&Bs[2][br * 64 + bc] = b_pf2;
        __syncthreads();

        // prefetch next tile (LDG in flight during compute below)
        if (kt + 32 < C_SZ) {
            int kn = kt + 32;
            a_pf0 = *(const float4*)&x[(size_t)(row0 + ar0) * C_SZ + kn + ac0];
            a_pf1 = *(const float4*)&x[(size_t)(row0 + ar1) * C_SZ + kn + ac1];
            b_pf0 = *(const float4*)&Wq[(kn + br) * H_SZ + bc];
            b_pf1 = *(const float4*)&Wk[(kn + br) * H_SZ + bc];
            b_pf2 = *(const float4*)&Wv[(kn + br) * H_SZ + bc];
        }

        #pragma unroll
        for (int kk = 0; kk < 32; kk += 4) {
            float4 av[4];
            #pragma unroll
            for (int i = 0; i < 4; i++)
                av[i] = *(const float4*)&As[(ty * 4 + i) * APAD + kk];
            #pragma unroll
            for (int q = 0; q < 4; q++) {
                ull_t a2[4];
                #pragma unroll
                for (int i = 0; i < 4; i++) {
                    float a = (q == 0) ? av[i].x : (q == 1) ? av[i].y
                            : (q == 2) ? av[i].z : av[i].w;
                    a2[i] = pack2(a, a);
                }
                #pragma unroll
                for (int m = 0; m < 3; m++) {
                    ulonglong2 b2 = *(const ulonglong2*)&Bs[m][(kk + q) * 64 + tx * 4];
                    #pragma unroll
                    for (int i = 0; i < 4; i++) {
                        ffma2(acc[m][i][0], a2[i], b2.x);
                        ffma2(acc[m][i][1], a2[i], b2.y);
                    }
                }
            }
        }
        __syncthreads();
    }

    // --- bias + store ---
    const float* biases[3] = { bq, bk, bv };
    float* outs[3] = { g_Q, g_K, g_V };
    #pragma unroll
    for (int m = 0; m < 3; m++) {
        ull_t blo = *(const ull_t*)&biases[m][tx * 4];
        ull_t bhi = *(const ull_t*)&biases[m][tx * 4 + 2];
        #pragma unroll
        for (int i = 0; i < 4; i++) {
            ulonglong2 st;
            st.x = add2(acc[m][i][0], blo);
            st.y = add2(acc[m][i][1], bhi);
            *(ulonglong2*)&outs[m][(size_t)(row0 + ty * 4 + i) * H_SZ + tx * 4] = st;
        }
    }
}

// ============================================================================
// Kernel 2: tiled flash attention. Grid = 4 query tiles x 512 batches.
// Block (jt, b): 64 queries, loops key tiles 0..jt. Both GEMMs (S=Q K^T and
// O+=P V) are cooperative 64x64x64 register-tiled f32x2 GEMMs; online softmax
// per row via half-warp bfly shuffles. All threads do equal work.
// ============================================================================
#define PAD 68    // smem row stride: 16B aligned, kills 4-row bank aliasing

__global__ __launch_bounds__(256) void attn_kernel(float* __restrict__ out)
{
    extern __shared__ __align__(16) float sm[];
    float* Qs  = sm;                 // [64 r][PAD]  (pre-scaled by SCALE)
    float* KsT = sm + 64 * PAD;      // [64 h][PAD c]  (transposed K tile)
    float* Vs  = sm + 2 * 64 * PAD;  // [64 c][PAD h]
    float* Ps  = sm + 3 * 64 * PAD;  // [64 r][PAD c]

    const int bid = blockIdx.x;
    const int jt  = 3 - (bid >> 9);    // long blocks scheduled first
    const int b   = bid & 511;
    const int tid = threadIdx.x;
    const int tx  = tid & 15;          // 4 cols tx*4..+3
    const int ty  = tid >> 4;          // 4 rows ty*4..+3
    const size_t base = (size_t)b * (T_SZ * H_SZ);
    const int q0 = jt << 6;

    // --- load Q tile (64x64), scaled ---
    {
        const float4* gq = (const float4*)(g_Q + base + (size_t)q0 * H_SZ);
        #pragma unroll
        for (int it = 0; it < 4; it++) {
            int u = tid + it * 256;
            int r = u >> 4, c4 = (u & 15) << 2;
            float4 v = gq[u];
            v.x *= SCALE; v.y *= SCALE; v.z *= SCALE; v.w *= SCALE;
            *(float4*)&Qs[r * PAD + c4] = v;
        }
    }

    ull_t acc_o[4][2];
    #pragma unroll
    for (int i = 0; i < 4; i++) { acc_o[i][0] = 0ULL; acc_o[i][1] = 0ULL; }
    float mrow[4] = { -1e30f, -1e30f, -1e30f, -1e30f };
    float lrow[4] = { 0.f, 0.f, 0.f, 0.f };

    for (int n = 0; n <= jt; n++) {
        __syncthreads();   // prev tile's O GEMM (and Q staging) drained
        // --- load K tile transposed + V tile ---
        const float4* gk = (const float4*)(g_K + base + ((size_t)n << 6) * H_SZ);
        const float4* gv = (const float4*)(g_V + base + ((size_t)n << 6) * H_SZ);
        #pragma unroll
        for (int it = 0; it < 4; it++) {
            int u = tid + it * 256;
            int r = u >> 4, c4 = (u & 15) << 2;
            float4 kv = gk[u];
            KsT[(c4 + 0) * PAD + r] = kv.x;
            KsT[(c4 + 1) * PAD + r] = kv.y;
            KsT[(c4 + 2) * PAD + r] = kv.z;
            KsT[(c4 + 3) * PAD + r] = kv.w;
            *(float4*)&Vs[r * PAD + c4] = gv[u];
        }
        __syncthreads();

        // --- S = Q @ K^T (4x4 micro-tile per thread) ---
        ull_t acc_s[4][2];
        #pragma unroll
        for (int i = 0; i < 4; i++) { acc_s[i][0] = 0ULL; acc_s[i][1] = 0ULL; }

        #pragma unroll 4
        for (int h = 0; h < 64; h += 4) {
            float4 av[4];
            #pragma unroll
            for (int i = 0; i < 4; i++)
                av[i] = *(const float4*)&Qs[(ty * 4 + i) * PAD + h];
            #pragma unroll
            for (int q = 0; q < 4; q++) {
                ulonglong2 b2 = *(const ulonglong2*)&KsT[(h + q) * PAD + (tx << 2)];
                #pragma unroll
                for (int i = 0; i < 4; i++) {
                    float a = (q == 0) ? av[i].x : (q == 1) ? av[i].y
                            : (q == 2) ? av[i].z : av[i].w;
                    ull_t a2 = pack2(a, a);
                    ffma2(acc_s[i][0], a2, b2.x);
                    ffma2(acc_s[i][1], a2, b2.y);
                }
            }
        }

        // --- online softmax per row + P store + O rescale ---
        #pragma unroll
        for (int i = 0; i < 4; i++) {
            float s0, s1, s2, s3;
            unpack2(acc_s[i][0], s0, s1);
            unpack2(acc_s[i][1], s2, s3);
            if (n == jt) {              // causal mask inside diagonal tile
                int r = (ty << 2) + i;
                int c = tx << 2;
                if (c + 0 > r) s0 = -1e30f;
                if (c + 1 > r) s1 = -1e30f;
                if (c + 2 > r) s2 = -1e30f;
                if (c + 3 > r) s3 = -1e30f;
            }
            float mx = fmaxf(fmaxf(s0, s1), fmaxf(s2, s3));
            mx = fmaxf(mx, __shfl_xor_sync(0xffffffffu, mx, 1));
            mx = fmaxf(mx, __shfl_xor_sync(0xffffffffu, mx, 2));
            mx = fmaxf(mx, __shfl_xor_sync(0xffffffffu, mx, 4));
            mx = fmaxf(mx, __shfl_xor_sync(0xffffffffu, mx, 8));
            float mnew = fmaxf(mrow[i], mx);
            float fac  = __expf(mrow[i] - mnew);
            mrow[i] = mnew;
            float p0 = __expf(s0 - mnew);
            float p1 = __expf(s1 - mnew);
            float p2 = __expf(s2 - mnew);
            float p3 = __expf(s3 - mnew);
            float ps = (p0 + p1) + (p2 + p3);
            ps += __shfl_xor_sync(0xffffffffu, ps, 1);
            ps += __shfl_xor_sync(0xffffffffu, ps, 2);
            ps += __shfl_xor_sync(0xffffffffu, ps, 4);
            ps += __shfl_xor_sync(0xffffffffu, ps, 8);
            lrow[i] = lrow[i] * fac + ps;
            ull_t f2 = pack2(fac, fac);
            acc_o[i][0] = mul2(acc_o[i][0], f2);
            acc_o[i][1] = mul2(acc_o[i][1], f2);
            float4 pv = make_float4(p0, p1, p2, p3);
            *(float4*)&Ps[((ty << 2) + i) * PAD + (tx << 2)] = pv;
        }
        __syncthreads();

        // --- O += P @ V ---
        #pragma unroll 4
        for (int c = 0; c < 64; c += 4) {
            float4 av[4];
            #pragma unroll
            for (int i = 0; i < 4; i++)
                av[i] = *(const float4*)&Ps[(ty * 4 + i) * PAD + c];
            #pragma unroll
            for (int q = 0; q < 4; q++) {
                ulonglong2 b2 = *(const ulonglong2*)&Vs[(c + q) * PAD + (tx << 2)];
                #pragma unroll
                for (int i = 0; i < 4; i++) {
                    float a = (q == 0) ? av[i].x : (q == 1) ? av[i].y
                            : (q == 2) ? av[i].z : av[i].w;
                    ull_t a2 = pack2(a, a);
                    ffma2(acc_o[i][0], a2, b2.x);
                    ffma2(acc_o[i][1], a2, b2.y);
                }
            }
        }
    }

    // --- normalize and store ---
    #pragma unroll
    for (int i = 0; i < 4; i++) {
        float inv = 1.0f / lrow[i];
        ull_t inv2 = pack2(inv, inv);
        ulonglong2 st;
        st.x = mul2(acc_o[i][0], inv2);
        st.y = mul2(acc_o[i][1], inv2);
        *(ulonglong2*)&out[base + (size_t)(q0 + ty * 4 + i) * H_SZ + (tx << 2)] = st;
    }
}

// ============================================================================
extern "C" void kernel_launch(void* const* d_in, const int* in_sizes, int n_in,
                              void* d_out, int out_size)
{
    const float* x  = (const float*)d_in[0];
    const float* Wq = (const float*)d_in[1];
    const float* bq = (const float*)d_in[2];
    const float* Wk = (const float*)d_in[3];
    const float* bk = (const float*)d_in[4];
    const float* Wv = (const float*)d_in[5];
    const float* bv = (const float*)d_in[6];
    float* out = (float*)d_out;

    const int attn_smem = 4 * 64 * PAD * (int)sizeof(float);  // 69,632 B

    static int smem_set = 0;
    if (!smem_set) {
        cudaFuncSetAttribute(attn_kernel,
                             cudaFuncAttributeMaxDynamicSharedMemorySize,
                             attn_smem);
        smem_set = 1;
    }

    // QKV projection: 131072 rows / 128 rows per block
    qkv_kernel<<<(B_SZ * T_SZ) / 128, 512>>>(x, Wq, bq, Wk, bk, Wv, bv);

    // Attention: 4 query tiles x 512 batches (longest tiles first)
    attn_kernel<<<4 * B_SZ, 256, attn_smem>>>(out);
}